// round 16
// baseline (speedup 1.0000x reference)
#include <cuda_runtime.h>
#include <cstdint>

#define DPC 90                       // 10 + 80 classes
#define GRID_S 7
#define TILE_CELLS 48
#define TILE_FLOATS (TILE_CELLS * DPC)        // 4320
#define TILE_F4     (TILE_FLOATS / 4)         // 1080
#define TILE_BYTES  (TILE_FLOATS * 4)         // 17280
#define STAGE_BYTES (2 * TILE_BYTES)          // 34560
#define NSTAGES 3
#define NTHREADS 256
#define NBLOCKS 296                           // 2 CTAs per SM

// accumulators: [0]=n_obj, [1]=coord_sum, [2]=conf_sum, [3]=class_sum
__device__ float g_acc[4];
__device__ unsigned int g_done;

__device__ __forceinline__ unsigned smem_u32(const void* p) {
    return (unsigned)__cvta_generic_to_shared(p);
}
__device__ __forceinline__ void mbar_init(unsigned addr, unsigned count) {
    asm volatile("mbarrier.init.shared.b64 [%0], %1;" :: "r"(addr), "r"(count) : "memory");
}
__device__ __forceinline__ void mbar_expect_tx(unsigned addr, unsigned bytes) {
    asm volatile("mbarrier.arrive.expect_tx.shared.b64 _, [%0], %1;"
                 :: "r"(addr), "r"(bytes) : "memory");
}
__device__ __forceinline__ void mbar_wait(unsigned addr, unsigned parity) {
    asm volatile(
        "{\n\t"
        ".reg .pred P;\n\t"
        "WAIT_%=:\n\t"
        "mbarrier.try_wait.parity.acquire.cta.shared::cta.b64 P, [%0], %1, 0x989680;\n\t"
        "@P bra DONE_%=;\n\t"
        "bra WAIT_%=;\n\t"
        "DONE_%=:\n\t"
        "}"
        :: "r"(addr), "r"(parity) : "memory");
}
__device__ __forceinline__ void bulk_copy(unsigned dst, const void* src,
                                          unsigned bytes, unsigned mbar) {
    asm volatile(
        "cp.async.bulk.shared::cta.global.mbarrier::complete_tx::bytes "
        "[%0], [%1], %2, [%3];"
        :: "r"(dst), "l"(src), "r"(bytes), "r"(mbar) : "memory");
}

__device__ __forceinline__ float iou_img(float cx1, float cy1, float w1, float h1,
                                         float cx2, float cy2, float w2, float h2) {
    float ix_min = fmaxf(cx1 - 0.5f * w1, cx2 - 0.5f * w2);
    float iy_min = fmaxf(cy1 - 0.5f * h1, cy2 - 0.5f * h2);
    float ix_max = fminf(cx1 + 0.5f * w1, cx2 + 0.5f * w2);
    float iy_max = fminf(cy1 + 0.5f * h1, cy2 + 0.5f * h2);
    float iw = fmaxf(ix_max - ix_min, 0.0f);
    float ih = fmaxf(iy_max - iy_min, 0.0f);
    float inter = iw * ih;
    float uni = w1 * h1 + w2 * h2 - inter;
    return inter / (uni + 1e-6f);
}

// one elected thread issues the whole tile as 2 bulk-TMA copies
__device__ __forceinline__ void issue_tile_tma(char* smem, unsigned mbar_addr,
                                               int stage, long tg,
                                               const float* __restrict__ pred,
                                               const float* __restrict__ tgt) {
    char* sbase = smem + stage * STAGE_BYTES;
    const char* gp = (const char*)pred + tg * (long)TILE_BYTES;
    const char* gt = (const char*)tgt  + tg * (long)TILE_BYTES;
    mbar_expect_tx(mbar_addr, STAGE_BYTES);
    bulk_copy(smem_u32(sbase),              gp, TILE_BYTES, mbar_addr);
    bulk_copy(smem_u32(sbase + TILE_BYTES), gt, TILE_BYTES, mbar_addr);
}

__global__ void __launch_bounds__(NTHREADS, 2)
yolo_loss_kernel(const float* __restrict__ pred,
                 const float* __restrict__ tgt,
                 float* __restrict__ out,
                 int ncells) {
    extern __shared__ char smem[];
    __shared__ __align__(8) uint64_t mbar[NSTAGES];
    __shared__ float s_red[8][4];

    const unsigned FULL = 0xffffffffu;
    const int tid  = threadIdx.x;
    const int lane = tid & 31;
    const int wid  = tid >> 5;
    const int nb   = gridDim.x;
    const int ntiles = ncells / TILE_CELLS;

    float a_n = 0.0f, a_co = 0.0f, a_cf = 0.0f, a_cl = 0.0f;

    // ---------- init barriers ----------
    if (tid == 0) {
        #pragma unroll
        for (int s = 0; s < NSTAGES; ++s) mbar_init(smem_u32(&mbar[s]), 1);
    }
    __syncthreads();

    // ---------- prologue: prefetch tiles 0,1 into stages 0,1 ----------
    if (tid == 0) {
        #pragma unroll
        for (int j = 0; j < NSTAGES - 1; ++j) {
            long tg = blockIdx.x + (long)j * nb;
            if (tg < ntiles)
                issue_tile_tma(smem, smem_u32(&mbar[j]), j, tg, pred, tgt);
        }
    }

    // ---------- main pipelined loop (lock-step, triple-buffered) ----------
    long i = 0;
    for (long tg = blockIdx.x; tg < ntiles; tg += nb, ++i) {
        __syncthreads();   // all threads done with stage (i+2)%3 (used at i-1)

        // refill stage (i+2)%3 with tile i+2
        long tg_pre = tg + 2 * (long)nb;
        if (tid == 0 && tg_pre < ntiles) {
            long u = i + 2;
            int st_pre = (int)(u % 3);
            issue_tile_tma(smem, smem_u32(&mbar[st_pre]), st_pre, tg_pre, pred, tgt);
        }

        // wait for tile i's data (stage i%3, parity (i/3)&1)
        int st = (int)(i % 3);
        mbar_wait(smem_u32(&mbar[st]), (unsigned)((i / 3) & 1));

        char* sb = smem + st * STAGE_BYTES;
        const float4* sp4 = (const float4*)sb;
        const float4* st4 = (const float4*)(sb + TILE_BYTES);
        const float*  sp  = (const float*)sb;
        const float*  stt = (const float*)(sb + TILE_BYTES);

        // ----- Phase A: class MSE over the whole tile (all 256 threads) -----
        float acc = 0.0f;
        #pragma unroll
        for (int k = 0; k < 5; ++k) {
            int idx = tid + k * NTHREADS;
            if (idx < TILE_F4) {
                float4 pv = sp4[idx];
                float4 tv = st4[idx];
                unsigned f  = (unsigned)(idx << 2);
                unsigned c0 = f / 90u;
                int e0 = (int)(f - 90u * c0);
                float tcv = stt[c0 * 90u + 4u];
                float w = (tcv == 1.0f) ? 1.0f : 0.0f;
                float w01 = (e0 >= 10) ? w : 0.0f;
                float w23 = (e0 >= 8 && e0 < 88) ? w : 0.0f;
                float d0 = pv.x - tv.x, d1 = pv.y - tv.y;
                float d2 = pv.z - tv.z, d3 = pv.w - tv.w;
                acc = fmaf(w01, fmaf(d0, d0, d1 * d1), acc);
                acc = fmaf(w23, fmaf(d2, d2, d3 * d3), acc);
            }
        }
        a_cl += acc;

        // ----- Phase B: box math, one thread per cell (threads 0..47) -----
        if (tid < TILE_CELLS) {
            const float* P = sp  + tid * DPC;
            const float* T = stt + tid * DPC;
            float bx1 = P[0], by1 = P[1], bw1 = P[2], bh1 = P[3], bc1 = P[4];
            float bx2 = P[5], by2 = P[6], bw2 = P[7], bh2 = P[8], bc2 = P[9];
            float tx = T[0], ty = T[1], tw = T[2], th = T[3], tcv = T[4];

            long cell = tg * TILE_CELLS + tid;
            int gx = (int)(cell % GRID_S);
            int gy = (int)((cell / GRID_S) % GRID_S);
            const float inv = 1.0f / (float)GRID_S;
            float fgx = (float)gx, fgy = (float)gy;

            float c1x = (fgx + bx1) * inv, c1y = (fgy + by1) * inv;
            float c2x = (fgx + bx2) * inv, c2y = (fgy + by2) * inv;
            float ctx = (fgx + tx)  * inv, cty = (fgy + ty)  * inv;

            float iou1 = iou_img(c1x, c1y, bw1, bh1, ctx, cty, tw, th);
            float iou2 = iou_img(c2x, c2y, bw2, bh2, ctx, cty, tw, th);
            bool r1sel = iou1 > iou2;

            float bx = r1sel ? bx1 : bx2;
            float by = r1sel ? by1 : by2;
            float bw = r1sel ? bw1 : bw2;
            float bh = r1sel ? bh1 : bh2;
            float bc = r1sel ? bc1 : bc2;

            float objf = (tcv == 1.0f) ? 1.0f : 0.0f;

            float dx = bx - tx, dy = by - ty;
            float dxy2 = dx * dx + dy * dy;
            float sw = sqrtf(fmaxf(bw, 1e-6f)) - sqrtf(fmaxf(tw, 1e-6f));
            float sh = sqrtf(fmaxf(bh, 1e-6f)) - sqrtf(fmaxf(th, 1e-6f));
            float coord_per = 0.5f * (dxy2 + sw * sw + sh * sh);

            float co = bc - 1.0f;
            float conf = (objf != 0.0f) ? (co * co)
                                        : 0.5f * (bc1 * bc1 + bc2 * bc2);

            a_n  += objf;
            a_co += coord_per * objf;
            a_cf += conf;
        }
    }

    // ---------- leftover cells (ncells % 48), handled by block 0 ----------
    int rem = ncells - ntiles * TILE_CELLS;
    if (blockIdx.x == 0 && tid < rem) {
        int cell = ntiles * TILE_CELLS + tid;
        const float* P = pred + (size_t)cell * DPC;
        const float* T = tgt  + (size_t)cell * DPC;
        float tcv = T[4];
        float objf = (tcv == 1.0f) ? 1.0f : 0.0f;

        float cs = 0.0f;
        for (int k = 10; k < DPC; ++k) {
            float d = P[k] - T[k];
            cs = fmaf(d, d, cs);
        }
        a_cl += cs * objf;

        float bx1 = P[0], by1 = P[1], bw1 = P[2], bh1 = P[3], bc1 = P[4];
        float bx2 = P[5], by2 = P[6], bw2 = P[7], bh2 = P[8], bc2 = P[9];
        float tx = T[0], ty = T[1], tw = T[2], th = T[3];

        int gx = cell % GRID_S;
        int gy = (cell / GRID_S) % GRID_S;
        const float inv = 1.0f / (float)GRID_S;
        float fgx = (float)gx, fgy = (float)gy;

        float iou1 = iou_img((fgx + bx1) * inv, (fgy + by1) * inv, bw1, bh1,
                             (fgx + tx) * inv,  (fgy + ty) * inv,  tw,  th);
        float iou2 = iou_img((fgx + bx2) * inv, (fgy + by2) * inv, bw2, bh2,
                             (fgx + tx) * inv,  (fgy + ty) * inv,  tw,  th);
        bool r1sel = iou1 > iou2;
        float bx = r1sel ? bx1 : bx2;
        float by = r1sel ? by1 : by2;
        float bw = r1sel ? bw1 : bw2;
        float bh = r1sel ? bh1 : bh2;
        float bc = r1sel ? bc1 : bc2;

        float dx = bx - tx, dy = by - ty;
        float dxy2 = dx * dx + dy * dy;
        float sw = sqrtf(fmaxf(bw, 1e-6f)) - sqrtf(fmaxf(tw, 1e-6f));
        float sh = sqrtf(fmaxf(bh, 1e-6f)) - sqrtf(fmaxf(th, 1e-6f));
        float coord_per = 0.5f * (dxy2 + sw * sw + sh * sh);
        float co = bc - 1.0f;
        float conf = (objf != 0.0f) ? (co * co) : 0.5f * (bc1 * bc1 + bc2 * bc2);

        a_n  += objf;
        a_co += coord_per * objf;
        a_cf += conf;
    }

    // ---------- warp reduction ----------
    #pragma unroll
    for (int off = 16; off; off >>= 1) {
        a_n  += __shfl_down_sync(FULL, a_n,  off);
        a_co += __shfl_down_sync(FULL, a_co, off);
        a_cf += __shfl_down_sync(FULL, a_cf, off);
        a_cl += __shfl_down_sync(FULL, a_cl, off);
    }
    if (lane == 0) {
        s_red[wid][0] = a_n;
        s_red[wid][1] = a_co;
        s_red[wid][2] = a_cf;
        s_red[wid][3] = a_cl;
    }
    __syncthreads();

    if (tid < 4) {
        float s = 0.0f;
        #pragma unroll
        for (int w = 0; w < 8; ++w) s += s_red[w][tid];
        atomicAdd(&g_acc[tid], s);
    }
    __syncthreads();

    // ---------- last-block finalize (self-resetting) ----------
    if (tid == 0) {
        __threadfence();
        unsigned int ticket = atomicAdd(&g_done, 1u);
        if (ticket == gridDim.x - 1) {
            __threadfence();
            volatile float* ga = g_acc;
            float n  = ga[0];
            float co = ga[1];
            float cf = ga[2];
            float cl = ga[3];
            float den = fmaxf(n, 1.0f);
            float conf_count = fmaxf(2.0f * (float)ncells - n, 1.0f);
            out[0] = 5.0f * (co / den) + cf / conf_count
                   + (cl * (1.0f / 80.0f)) / den;
            ga[0] = 0.0f; ga[1] = 0.0f; ga[2] = 0.0f; ga[3] = 0.0f;
            __threadfence();
            g_done = 0u;
        }
    }
}

extern "C" void kernel_launch(void* const* d_in, const int* in_sizes, int n_in,
                              void* d_out, int out_size) {
    const float* pred = (const float*)d_in[0];
    const float* tgt  = (const float*)d_in[1];
    float* out = (float*)d_out;

    int ncells = in_sizes[0] / DPC;    // B * S * S

    cudaFuncSetAttribute(yolo_loss_kernel,
                         cudaFuncAttributeMaxDynamicSharedMemorySize,
                         NSTAGES * STAGE_BYTES);

    yolo_loss_kernel<<<NBLOCKS, NTHREADS, NSTAGES * STAGE_BYTES>>>(
        pred, tgt, out, ncells);
}

// round 17
// speedup vs baseline: 1.5744x; 1.5744x over previous
#include <cuda_runtime.h>
#include <cstdint>

#define DPC 90            // 10 + 80 classes
#define GRID_S 7

// accumulators: [0]=n_obj, [1]=coord_sum, [2]=conf_sum, [3]=class_sum
__device__ float g_acc[4];
__device__ unsigned int g_done;

__device__ __forceinline__ float iou_img(float cx1, float cy1, float w1, float h1,
                                         float cx2, float cy2, float w2, float h2) {
    float ix_min = fmaxf(cx1 - 0.5f * w1, cx2 - 0.5f * w2);
    float iy_min = fmaxf(cy1 - 0.5f * h1, cy2 - 0.5f * h2);
    float ix_max = fminf(cx1 + 0.5f * w1, cx2 + 0.5f * w2);
    float iy_max = fminf(cy1 + 0.5f * h1, cy2 + 0.5f * h2);
    float iw = fmaxf(ix_max - ix_min, 0.0f);
    float ih = fmaxf(iy_max - iy_min, 0.0f);
    float inter = iw * ih;
    float uni = w1 * h1 + w2 * h2 - inter;
    return inter / (uni + 1e-6f);
}

__global__ void __launch_bounds__(256)
yolo_loss_kernel(const float* __restrict__ pred,
                 const float* __restrict__ tgt,
                 float* __restrict__ out,
                 int ncells) {
    const unsigned FULL = 0xffffffffu;
    const int lane  = threadIdx.x & 31;
    const int wid   = threadIdx.x >> 5;
    const int gwarp = blockIdx.x * 8 + wid;
    const int nwarps = gridDim.x * 8;
    const int nchunks = (ncells + 31) >> 5;

    __shared__ float s_red[8][4];

    float a_n = 0.0f, a_co = 0.0f, a_cf = 0.0f, a_cl = 0.0f;

    for (int chunk = gwarp; chunk < nchunks; chunk += nwarps) {
        const int base = chunk << 5;
        const int cell = base + lane;
        const bool valid = cell < ncells;

        const float* P = pred + (size_t)cell * DPC;
        const float* T = tgt  + (size_t)cell * DPC;

        // ---- always-needed gathers (sectors 0-1 of pred, sector 0 of tgt) ----
        float t4 = valid ? __ldg(T + 4) : 0.0f;
        bool obj = valid && (t4 == 1.0f);
        float2 p45 = valid ? *(const float2*)(P + 4) : make_float2(0.f, 0.f);
        float2 p89 = valid ? *(const float2*)(P + 8) : make_float2(0.f, 0.f);

        unsigned mask = __ballot_sync(FULL, obj);

        if (valid) {
            if (obj) {
                // full box math only for obj cells
                float2 p01 = *(const float2*)(P + 0);
                float2 p23 = *(const float2*)(P + 2);
                float2 p67 = *(const float2*)(P + 6);
                float2 t01 = *(const float2*)(T + 0);
                float2 t23 = *(const float2*)(T + 2);

                float bx1 = p01.x, by1 = p01.y, bw1 = p23.x, bh1 = p23.y, bc1 = p45.x;
                float bx2 = p45.y, by2 = p67.x, bw2 = p67.y, bh2 = p89.x, bc2 = p89.y;
                float tx = t01.x, ty = t01.y, tw = t23.x, th = t23.y;

                int gx = cell % GRID_S;
                int gy = (cell / GRID_S) % GRID_S;
                const float inv = 1.0f / (float)GRID_S;
                float fgx = (float)gx, fgy = (float)gy;

                float c1x = (fgx + bx1) * inv, c1y = (fgy + by1) * inv;
                float c2x = (fgx + bx2) * inv, c2y = (fgy + by2) * inv;
                float ctx = (fgx + tx)  * inv, cty = (fgy + ty)  * inv;

                float iou1 = iou_img(c1x, c1y, bw1, bh1, ctx, cty, tw, th);
                float iou2 = iou_img(c2x, c2y, bw2, bh2, ctx, cty, tw, th);
                bool r1sel = iou1 > iou2;

                float bx = r1sel ? bx1 : bx2;
                float by = r1sel ? by1 : by2;
                float bw = r1sel ? bw1 : bw2;
                float bh = r1sel ? bh1 : bh2;
                float bc = r1sel ? bc1 : bc2;

                float dx = bx - tx, dy = by - ty;
                float dxy2 = dx * dx + dy * dy;
                float sw = sqrtf(fmaxf(bw, 1e-6f)) - sqrtf(fmaxf(tw, 1e-6f));
                float sh = sqrtf(fmaxf(bh, 1e-6f)) - sqrtf(fmaxf(th, 1e-6f));
                float coord_per = 0.5f * (dxy2 + sw * sw + sh * sh);

                float co = bc - 1.0f;
                a_n  += 1.0f;
                a_co += coord_per;
                a_cf += co * co;
            } else {
                // noobj conf: only p[4], p[9]
                a_cf += 0.5f * (p45.x * p45.x + p89.y * p89.y);
            }
        }

        // ---- class MSE: warp-cooperative, OBJ CELLS ONLY (coalesced) ----
        while (mask) {
            int c = __ffs(mask) - 1;
            mask &= mask - 1;
            const float* Pc = pred + (size_t)(base + c) * DPC + 10;
            const float* Tc = tgt  + (size_t)(base + c) * DPC + 10;
            float d0 = __ldg(Pc + lane)      - __ldg(Tc + lane);
            float d1 = __ldg(Pc + lane + 32) - __ldg(Tc + lane + 32);
            float acc = fmaf(d0, d0, d1 * d1);
            if (lane < 16) {
                float d2 = __ldg(Pc + lane + 64) - __ldg(Tc + lane + 64);
                acc = fmaf(d2, d2, acc);
            }
            a_cl += acc;              // per-lane partial; reduced at the end
        }
    }

    // ---------- warp reduction ----------
    #pragma unroll
    for (int off = 16; off; off >>= 1) {
        a_n  += __shfl_down_sync(FULL, a_n,  off);
        a_co += __shfl_down_sync(FULL, a_co, off);
        a_cf += __shfl_down_sync(FULL, a_cf, off);
        a_cl += __shfl_down_sync(FULL, a_cl, off);
    }
    if (lane == 0) {
        s_red[wid][0] = a_n;
        s_red[wid][1] = a_co;
        s_red[wid][2] = a_cf;
        s_red[wid][3] = a_cl;
    }
    __syncthreads();

    if (threadIdx.x < 4) {
        float s = 0.0f;
        #pragma unroll
        for (int w = 0; w < 8; ++w) s += s_red[w][threadIdx.x];
        atomicAdd(&g_acc[threadIdx.x], s);
    }
    __syncthreads();

    // ---------- last-block finalize (self-resetting) ----------
    if (threadIdx.x == 0) {
        __threadfence();
        unsigned int ticket = atomicAdd(&g_done, 1u);
        if (ticket == gridDim.x - 1) {
            __threadfence();
            volatile float* ga = g_acc;
            float n  = ga[0];
            float co = ga[1];
            float cf = ga[2];
            float cl = ga[3];
            float den = fmaxf(n, 1.0f);
            float conf_count = fmaxf(2.0f * (float)ncells - n, 1.0f);
            out[0] = 5.0f * (co / den) + cf / conf_count
                   + (cl * (1.0f / 80.0f)) / den;
            ga[0] = 0.0f; ga[1] = 0.0f; ga[2] = 0.0f; ga[3] = 0.0f;
            __threadfence();
            g_done = 0u;
        }
    }
}

extern "C" void kernel_launch(void* const* d_in, const int* in_sizes, int n_in,
                              void* d_out, int out_size) {
    const float* pred = (const float*)d_in[0];
    const float* tgt  = (const float*)d_in[1];
    float* out = (float*)d_out;

    int ncells  = in_sizes[0] / DPC;       // B * S * S
    int nchunks = (ncells + 31) / 32;      // one 32-cell chunk per warp
    int blocks  = (nchunks + 7) / 8;       // 8 warps per block

    yolo_loss_kernel<<<blocks, 256>>>(pred, tgt, out, ncells);
}